// round 1
// baseline (speedup 1.0000x reference)
#include <cuda_runtime.h>
#include <math.h>

// Problem constants
#define E_DIM 1024
#define BATCH 4
#define SEQ 2048
#define M_TOT (BATCH * SEQ)   // 8192

// ---------------- scratch (allocation-free: __device__ globals) -------------
__device__ float g_qkv[(size_t)M_TOT * 3 * E_DIM];     // 96 MB  (B*S, 3E)
__device__ float g_scores[(size_t)BATCH * SEQ * SEQ];  // 64 MB  (B, S, S)
__device__ float g_attn[(size_t)M_TOT * E_DIM];        // 32 MB  (B*S, E)
__device__ float g_out[(size_t)M_TOT * E_DIM];         // 32 MB  (B*S, E)

// ---------------- tiled SGEMM, C = alpha * A(MxK) * B^T(NxK) ----------------
// A row-major (lda = K stride), B row-major (N,K) (ldb), C row-major (ldc).
// EPI = 0: plain store. EPI = 1: C = Comp * sigmoid(acc)   (gated epilogue)
template <int EPI>
__global__ __launch_bounds__(256)
void sgemm_nt(const float* __restrict__ A, const float* __restrict__ B,
              float* __restrict__ C, const float* __restrict__ Comp,
              int M, int N, int K, int lda, int ldb, int ldc, float alpha,
              long bsA, long bsB, long bsC)
{
    A += (long)blockIdx.z * bsA;
    B += (long)blockIdx.z * bsB;
    C += (long)blockIdx.z * bsC;

    const int BM = 128, BN = 128, BK = 16;
    __shared__ float As[BK][BM + 4];
    __shared__ float Bs[BK][BN + 4];

    const int tid = threadIdx.x;
    const int bm = blockIdx.y * BM;
    const int bn = blockIdx.x * BN;

    const int tx = tid & 15;   // 0..15 -> 8 output cols each
    const int ty = tid >> 4;   // 0..15 -> 8 output rows each

    const int lrow = tid >> 2;          // 0..63
    const int lcol = (tid & 3) * 4;     // 0,4,8,12

    float acc[8][8];
    #pragma unroll
    for (int i = 0; i < 8; i++)
        #pragma unroll
        for (int j = 0; j < 8; j++) acc[i][j] = 0.f;

    for (int k0 = 0; k0 < K; k0 += BK) {
        #pragma unroll
        for (int r = 0; r < 2; r++) {
            float4 av = *(const float4*)&A[(long)(bm + lrow + r * 64) * lda + k0 + lcol];
            As[lcol + 0][lrow + r * 64] = av.x;
            As[lcol + 1][lrow + r * 64] = av.y;
            As[lcol + 2][lrow + r * 64] = av.z;
            As[lcol + 3][lrow + r * 64] = av.w;
            float4 bv = *(const float4*)&B[(long)(bn + lrow + r * 64) * ldb + k0 + lcol];
            Bs[lcol + 0][lrow + r * 64] = bv.x;
            Bs[lcol + 1][lrow + r * 64] = bv.y;
            Bs[lcol + 2][lrow + r * 64] = bv.z;
            Bs[lcol + 3][lrow + r * 64] = bv.w;
        }
        __syncthreads();

        #pragma unroll
        for (int k = 0; k < BK; k++) {
            float a[8], b[8];
            #pragma unroll
            for (int i = 0; i < 8; i++) a[i] = As[k][ty * 8 + i];
            #pragma unroll
            for (int j = 0; j < 8; j++) b[j] = Bs[k][tx * 8 + j];
            #pragma unroll
            for (int i = 0; i < 8; i++)
                #pragma unroll
                for (int j = 0; j < 8; j++) acc[i][j] = fmaf(a[i], b[j], acc[i][j]);
        }
        __syncthreads();
    }

    #pragma unroll
    for (int i = 0; i < 8; i++) {
        const long row = bm + ty * 8 + i;
        #pragma unroll
        for (int j = 0; j < 8; j++) {
            const long col = bn + tx * 8 + j;
            float v = alpha * acc[i][j];
            if (EPI == 0) {
                C[row * ldc + col] = v;
            } else {
                float o = Comp[row * ldc + col];
                C[row * ldc + col] = o * (1.0f / (1.0f + expf(-v)));
            }
        }
    }
}

// ---------------- tiled SGEMM, C = A(MxK) * B(KxN) ---------------------------
__global__ __launch_bounds__(256)
void sgemm_nn(const float* __restrict__ A, const float* __restrict__ B,
              float* __restrict__ C,
              int M, int N, int K, int lda, int ldb, int ldc,
              long bsA, long bsB, long bsC)
{
    A += (long)blockIdx.z * bsA;
    B += (long)blockIdx.z * bsB;
    C += (long)blockIdx.z * bsC;

    const int BM = 128, BN = 128, BK = 16;
    __shared__ float As[BK][BM + 4];
    __shared__ float Bs[BK][BN + 4];

    const int tid = threadIdx.x;
    const int bm = blockIdx.y * BM;
    const int bn = blockIdx.x * BN;

    const int tx = tid & 15;
    const int ty = tid >> 4;

    const int arow = tid >> 2;          // 0..63
    const int acol = (tid & 3) * 4;     // 0,4,8,12
    const int brow = tid >> 5;          // 0..7
    const int bcol = (tid & 31) * 4;    // 0..124

    float acc[8][8];
    #pragma unroll
    for (int i = 0; i < 8; i++)
        #pragma unroll
        for (int j = 0; j < 8; j++) acc[i][j] = 0.f;

    for (int k0 = 0; k0 < K; k0 += BK) {
        #pragma unroll
        for (int r = 0; r < 2; r++) {
            float4 av = *(const float4*)&A[(long)(bm + arow + r * 64) * lda + k0 + acol];
            As[acol + 0][arow + r * 64] = av.x;
            As[acol + 1][arow + r * 64] = av.y;
            As[acol + 2][arow + r * 64] = av.z;
            As[acol + 3][arow + r * 64] = av.w;
            float4 bv = *(const float4*)&B[(long)(k0 + brow + r * 8) * ldb + bn + bcol];
            *(float4*)&Bs[brow + r * 8][bcol] = bv;
        }
        __syncthreads();

        #pragma unroll
        for (int k = 0; k < BK; k++) {
            float a[8], b[8];
            #pragma unroll
            for (int i = 0; i < 8; i++) a[i] = As[k][ty * 8 + i];
            #pragma unroll
            for (int j = 0; j < 8; j++) b[j] = Bs[k][tx * 8 + j];
            #pragma unroll
            for (int i = 0; i < 8; i++)
                #pragma unroll
                for (int j = 0; j < 8; j++) acc[i][j] = fmaf(a[i], b[j], acc[i][j]);
        }
        __syncthreads();
    }

    #pragma unroll
    for (int i = 0; i < 8; i++) {
        const long row = bm + ty * 8 + i;
        #pragma unroll
        for (int j = 0; j < 8; j++) {
            const long col = bn + tx * 8 + j;
            C[row * ldc + col] = acc[i][j];
        }
    }
}

// ---------------- row softmax over 2048-wide rows ---------------------------
__global__ __launch_bounds__(256)
void softmax_rows_2048(float* __restrict__ scores)
{
    float4* row = (float4*)(scores + (size_t)blockIdx.x * SEQ);
    const int tid = threadIdx.x;
    __shared__ float red[8];

    float4 v0 = row[tid];
    float4 v1 = row[tid + 256];

    float m = fmaxf(fmaxf(fmaxf(v0.x, v0.y), fmaxf(v0.z, v0.w)),
                    fmaxf(fmaxf(v1.x, v1.y), fmaxf(v1.z, v1.w)));
    #pragma unroll
    for (int o = 16; o > 0; o >>= 1) m = fmaxf(m, __shfl_xor_sync(0xffffffffu, m, o));
    if ((tid & 31) == 0) red[tid >> 5] = m;
    __syncthreads();
    float bm = red[0];
    #pragma unroll
    for (int i = 1; i < 8; i++) bm = fmaxf(bm, red[i]);
    __syncthreads();

    v0.x = expf(v0.x - bm); v0.y = expf(v0.y - bm);
    v0.z = expf(v0.z - bm); v0.w = expf(v0.w - bm);
    v1.x = expf(v1.x - bm); v1.y = expf(v1.y - bm);
    v1.z = expf(v1.z - bm); v1.w = expf(v1.w - bm);

    float s = v0.x + v0.y + v0.z + v0.w + v1.x + v1.y + v1.z + v1.w;
    #pragma unroll
    for (int o = 16; o > 0; o >>= 1) s += __shfl_xor_sync(0xffffffffu, s, o);
    if ((tid & 31) == 0) red[tid >> 5] = s;
    __syncthreads();
    float tot = 0.f;
    #pragma unroll
    for (int i = 0; i < 8; i++) tot += red[i];
    const float inv = 1.0f / tot;

    v0.x *= inv; v0.y *= inv; v0.z *= inv; v0.w *= inv;
    v1.x *= inv; v1.y *= inv; v1.z *= inv; v1.w *= inv;
    row[tid] = v0;
    row[tid + 256] = v1;
}

// ---------------- launch -----------------------------------------------------
extern "C" void kernel_launch(void* const* d_in, const int* in_sizes, int n_in,
                              void* d_out, int out_size)
{
    const float* w_qkv = (const float*)d_in[0];  // (3E, E)
    const float* w_out = (const float*)d_in[1];  // (E, E)
    const float* x     = (const float*)d_in[2];  // (B, S, E)
    const float* g_w   = (const float*)d_in[3];  // (E, E)
    float* out = (float*)d_out;                  // (B, S, E)

    float *qkv, *sc, *ao, *oo;
    cudaGetSymbolAddress((void**)&qkv, g_qkv);
    cudaGetSymbolAddress((void**)&sc,  g_scores);
    cudaGetSymbolAddress((void**)&ao,  g_attn);
    cudaGetSymbolAddress((void**)&oo,  g_out);

    const float scale = 0.125f;  // 1/sqrt(HEAD_DIM=64)

    // 1) QKV projection: (8192,1024) x (3072,1024)^T -> (8192,3072)
    sgemm_nt<0><<<dim3(3 * E_DIM / 128, M_TOT / 128, 1), 256>>>(
        x, w_qkv, qkv, nullptr,
        M_TOT, 3 * E_DIM, E_DIM, E_DIM, E_DIM, 3 * E_DIM, 1.0f, 0, 0, 0);

    // 2) scores = scale * q @ k^T, batched over B
    sgemm_nt<0><<<dim3(SEQ / 128, SEQ / 128, BATCH), 256>>>(
        qkv + 0, qkv + E_DIM, sc, nullptr,
        SEQ, SEQ, E_DIM, 3 * E_DIM, 3 * E_DIM, SEQ, scale,
        (long)SEQ * 3 * E_DIM, (long)SEQ * 3 * E_DIM, (long)SEQ * SEQ);

    // 3) row softmax (8192 rows of 2048)
    softmax_rows_2048<<<BATCH * SEQ, 256>>>(sc);

    // 4) attn_out = attn @ v, batched over B
    sgemm_nn<<<dim3(E_DIM / 128, SEQ / 128, BATCH), 256>>>(
        sc, qkv + 2 * E_DIM, ao,
        SEQ, E_DIM, SEQ, SEQ, 3 * E_DIM, E_DIM,
        (long)SEQ * SEQ, (long)SEQ * 3 * E_DIM, (long)SEQ * E_DIM);

    // 5) out = attn_out @ w_out^T
    sgemm_nt<0><<<dim3(E_DIM / 128, M_TOT / 128, 1), 256>>>(
        ao, w_out, oo, nullptr,
        M_TOT, E_DIM, E_DIM, E_DIM, E_DIM, E_DIM, 1.0f, 0, 0, 0);

    // 6) final = out * sigmoid(out @ gate_w^T)   (gated epilogue)
    sgemm_nt<1><<<dim3(E_DIM / 128, M_TOT / 128, 1), 256>>>(
        oo, g_w, out, oo,
        M_TOT, E_DIM, E_DIM, E_DIM, E_DIM, E_DIM, 1.0f, 0, 0, 0);
}

// round 2
// speedup vs baseline: 2.3620x; 2.3620x over previous
#include <cuda_runtime.h>
#include <math.h>
#include <stdint.h>

#define E_DIM 1024
#define BATCH 4
#define SEQ 2048
#define M_TOT (BATCH * SEQ)   // 8192

// ---------------- scratch (allocation-free: __device__ globals) -------------
__device__ float g_qkv[(size_t)M_TOT * 3 * E_DIM];     // 96 MB
__device__ float g_scores[(size_t)BATCH * SEQ * SEQ];  // 64 MB
__device__ float g_attn[(size_t)M_TOT * E_DIM];        // 32 MB
__device__ float g_out[(size_t)M_TOT * E_DIM];         // 32 MB

// ---------------- smem geometry ----------------------------------------------
#define A_STRIDE   36    // 32 k + 4 pad (16B-aligned rows, conflict-free frags)
#define BNT_STRIDE 36
#define BNN_STRIDE 132   // 128 n + 4 pad
#define A_STAGE (128 * A_STRIDE)   // 4608 floats
#define B_STAGE (128 * BNT_STRIDE) // 4608 floats (>= 32*132 = 4224 for NN)
#define SMEM_FLOATS (2 * (A_STAGE + B_STAGE))
#define SMEM_BYTES (SMEM_FLOATS * 4)  // 73728 B

// ---------------- PTX helpers -------------------------------------------------
__device__ __forceinline__ uint32_t f2tf(float f) {
    uint32_t u;
    asm("cvt.rna.tf32.f32 %0, %1;" : "=r"(u) : "f"(f));
    return u;
}

__device__ __forceinline__ void cpa16(void* dst_smem, const float* src) {
    uint32_t d = (uint32_t)__cvta_generic_to_shared(dst_smem);
    asm volatile("cp.async.cg.shared.global [%0], [%1], 16;" :: "r"(d), "l"(src));
}
#define CP_COMMIT() asm volatile("cp.async.commit_group;")
#define CP_WAIT(n)  asm volatile("cp.async.wait_group %0;" :: "n"(n))

__device__ __forceinline__ void mma8(float c[4], const uint32_t a[4], const uint32_t b[2]) {
    asm volatile(
        "mma.sync.aligned.m16n8k8.row.col.f32.tf32.tf32.f32 "
        "{%0,%1,%2,%3}, {%4,%5,%6,%7}, {%8,%9}, {%0,%1,%2,%3};"
        : "+f"(c[0]), "+f"(c[1]), "+f"(c[2]), "+f"(c[3])
        : "r"(a[0]), "r"(a[1]), "r"(a[2]), "r"(a[3]), "r"(b[0]), "r"(b[1]));
}

// ---------------- tf32 tensor-core GEMM --------------------------------------
// C(M,N) = alpha * A(M,K) * op(B),  all row-major fp32 in gmem.
// TRANS_B=1: B is (N,K), compute A*B^T.  TRANS_B=0: B is (K,N), compute A*B.
// EPI=1: C = Comp * sigmoid(alpha*acc)   (gated epilogue)
// Block tile 128x128x32, 256 threads, warps 2(m) x 4(n), warp tile 64x32.
template <int TRANS_B, int EPI>
__global__ __launch_bounds__(256)
void mm_tf32(const float* __restrict__ A, const float* __restrict__ B,
             float* __restrict__ C, const float* __restrict__ Comp,
             int K, int lda, int ldb, int ldc, float alpha,
             long bsA, long bsB, long bsC)
{
    extern __shared__ float sm[];
    A += (long)blockIdx.z * bsA;
    B += (long)blockIdx.z * bsB;
    C += (long)blockIdx.z * bsC;

    const int tid  = threadIdx.x;
    const int lane = tid & 31;
    const int warp = tid >> 5;
    const int bm = blockIdx.y * 128;
    const int bn = blockIdx.x * 128;
    const int wm = (warp & 1) * 64;
    const int wn = (warp >> 1) * 32;
    const int g = lane >> 2;   // 0..7
    const int t = lane & 3;    // 0..3

    float* AsBuf[2] = { sm, sm + A_STAGE };
    float* BsBuf[2] = { sm + 2 * A_STAGE, sm + 2 * A_STAGE + B_STAGE };

    float acc[4][4][4];
    #pragma unroll
    for (int mt = 0; mt < 4; mt++)
        #pragma unroll
        for (int nt = 0; nt < 4; nt++)
            #pragma unroll
            for (int i = 0; i < 4; i++) acc[mt][nt][i] = 0.f;

    auto load_tile = [&](int buf, int k0) {
        // A: 128 rows x 32 k  (1024 16B-chunks, 4 per thread)
        #pragma unroll
        for (int i = 0; i < 4; i++) {
            int idx = tid + i * 256;
            int row = idx >> 3;
            int kc  = (idx & 7) << 2;
            cpa16(&AsBuf[buf][row * A_STRIDE + kc],
                  A + (long)(bm + row) * lda + k0 + kc);
        }
        if (TRANS_B) {
            // B (N,K): 128 rows x 32 k -> Bs[n][k]
            #pragma unroll
            for (int i = 0; i < 4; i++) {
                int idx = tid + i * 256;
                int row = idx >> 3;
                int kc  = (idx & 7) << 2;
                cpa16(&BsBuf[buf][row * BNT_STRIDE + kc],
                      B + (long)(bn + row) * ldb + k0 + kc);
            }
        } else {
            // B (K,N): 32 rows x 128 n -> Bs[k][n]
            #pragma unroll
            for (int i = 0; i < 4; i++) {
                int idx = tid + i * 256;
                int kr = idx >> 5;
                int nc = (idx & 31) << 2;
                cpa16(&BsBuf[buf][kr * BNN_STRIDE + nc],
                      B + (long)(k0 + kr) * ldb + bn + nc);
            }
        }
    };

    const int KT = K >> 5;
    load_tile(0, 0);
    CP_COMMIT();

    for (int kt = 0; kt < KT; kt++) {
        if (kt + 1 < KT) {
            load_tile((kt + 1) & 1, (kt + 1) << 5);
            CP_COMMIT();
            CP_WAIT(1);
        } else {
            CP_WAIT(0);
        }
        __syncthreads();

        const float* Af = AsBuf[kt & 1];
        const float* Bf = BsBuf[kt & 1];

        #pragma unroll
        for (int kk = 0; kk < 32; kk += 8) {
            uint32_t af[4][4], bf[4][2];
            #pragma unroll
            for (int mt = 0; mt < 4; mt++) {
                const float* ap = Af + (wm + mt * 16 + g) * A_STRIDE + kk + t;
                af[mt][0] = f2tf(ap[0]);
                af[mt][1] = f2tf(ap[8 * A_STRIDE]);
                af[mt][2] = f2tf(ap[4]);
                af[mt][3] = f2tf(ap[8 * A_STRIDE + 4]);
            }
            #pragma unroll
            for (int nt = 0; nt < 4; nt++) {
                if (TRANS_B) {
                    const float* bp = Bf + (wn + nt * 8 + g) * BNT_STRIDE + kk + t;
                    bf[nt][0] = f2tf(bp[0]);
                    bf[nt][1] = f2tf(bp[4]);
                } else {
                    const float* bp = Bf + (kk + t) * BNN_STRIDE + wn + nt * 8 + g;
                    bf[nt][0] = f2tf(bp[0]);
                    bf[nt][1] = f2tf(bp[4 * BNN_STRIDE]);
                }
            }
            #pragma unroll
            for (int mt = 0; mt < 4; mt++)
                #pragma unroll
                for (int nt = 0; nt < 4; nt++)
                    mma8(acc[mt][nt], af[mt], bf[nt]);
        }
        __syncthreads();
    }

    // epilogue
    #pragma unroll
    for (int mt = 0; mt < 4; mt++) {
        #pragma unroll
        for (int nt = 0; nt < 4; nt++) {
            const long r = bm + wm + mt * 16 + g;
            const long c = bn + wn + nt * 8 + 2 * t;
            float v0 = acc[mt][nt][0] * alpha;
            float v1 = acc[mt][nt][1] * alpha;
            float v2 = acc[mt][nt][2] * alpha;
            float v3 = acc[mt][nt][3] * alpha;
            if (EPI) {
                float2 o0 = *(const float2*)&Comp[r * ldc + c];
                float2 o1 = *(const float2*)&Comp[(r + 8) * ldc + c];
                v0 = o0.x / (1.f + expf(-v0));
                v1 = o0.y / (1.f + expf(-v1));
                v2 = o1.x / (1.f + expf(-v2));
                v3 = o1.y / (1.f + expf(-v3));
            }
            *(float2*)&C[r * ldc + c]       = make_float2(v0, v1);
            *(float2*)&C[(r + 8) * ldc + c] = make_float2(v2, v3);
        }
    }
}

// ---------------- row softmax over 2048-wide rows ---------------------------
__global__ __launch_bounds__(256)
void softmax_rows_2048(float* __restrict__ scores)
{
    float4* row = (float4*)(scores + (size_t)blockIdx.x * SEQ);
    const int tid = threadIdx.x;
    __shared__ float red[8];

    float4 v0 = row[tid];
    float4 v1 = row[tid + 256];

    float m = fmaxf(fmaxf(fmaxf(v0.x, v0.y), fmaxf(v0.z, v0.w)),
                    fmaxf(fmaxf(v1.x, v1.y), fmaxf(v1.z, v1.w)));
    #pragma unroll
    for (int o = 16; o > 0; o >>= 1) m = fmaxf(m, __shfl_xor_sync(0xffffffffu, m, o));
    if ((tid & 31) == 0) red[tid >> 5] = m;
    __syncthreads();
    float bm = red[0];
    #pragma unroll
    for (int i = 1; i < 8; i++) bm = fmaxf(bm, red[i]);
    __syncthreads();

    v0.x = expf(v0.x - bm); v0.y = expf(v0.y - bm);
    v0.z = expf(v0.z - bm); v0.w = expf(v0.w - bm);
    v1.x = expf(v1.x - bm); v1.y = expf(v1.y - bm);
    v1.z = expf(v1.z - bm); v1.w = expf(v1.w - bm);

    float s = v0.x + v0.y + v0.z + v0.w + v1.x + v1.y + v1.z + v1.w;
    #pragma unroll
    for (int o = 16; o > 0; o >>= 1) s += __shfl_xor_sync(0xffffffffu, s, o);
    if ((tid & 31) == 0) red[tid >> 5] = s;
    __syncthreads();
    float tot = 0.f;
    #pragma unroll
    for (int i = 0; i < 8; i++) tot += red[i];
    const float inv = 1.0f / tot;

    v0.x *= inv; v0.y *= inv; v0.z *= inv; v0.w *= inv;
    v1.x *= inv; v1.y *= inv; v1.z *= inv; v1.w *= inv;
    row[tid] = v0;
    row[tid + 256] = v1;
}

// ---------------- launch -----------------------------------------------------
extern "C" void kernel_launch(void* const* d_in, const int* in_sizes, int n_in,
                              void* d_out, int out_size)
{
    const float* w_qkv = (const float*)d_in[0];  // (3E, E)
    const float* w_out = (const float*)d_in[1];  // (E, E)
    const float* x     = (const float*)d_in[2];  // (B, S, E)
    const float* g_w   = (const float*)d_in[3];  // (E, E)
    float* out = (float*)d_out;                  // (B, S, E)

    float *qkv, *sc, *ao, *oo;
    cudaGetSymbolAddress((void**)&qkv, g_qkv);
    cudaGetSymbolAddress((void**)&sc,  g_scores);
    cudaGetSymbolAddress((void**)&ao,  g_attn);
    cudaGetSymbolAddress((void**)&oo,  g_out);

    cudaFuncSetAttribute(mm_tf32<1, 0>, cudaFuncAttributeMaxDynamicSharedMemorySize, SMEM_BYTES);
    cudaFuncSetAttribute(mm_tf32<0, 0>, cudaFuncAttributeMaxDynamicSharedMemorySize, SMEM_BYTES);
    cudaFuncSetAttribute(mm_tf32<1, 1>, cudaFuncAttributeMaxDynamicSharedMemorySize, SMEM_BYTES);

    const float scale = 0.125f;  // 1/sqrt(HEAD_DIM=64)

    // 1) qkv = x @ w_qkv^T : (8192,1024) x (3072,1024)^T
    mm_tf32<1, 0><<<dim3(24, 64, 1), 256, SMEM_BYTES>>>(
        x, w_qkv, qkv, nullptr, E_DIM, E_DIM, E_DIM, 3 * E_DIM, 1.0f, 0, 0, 0);

    // 2) scores = scale * q @ k^T, batched over B
    mm_tf32<1, 0><<<dim3(16, 16, BATCH), 256, SMEM_BYTES>>>(
        qkv, qkv + E_DIM, sc, nullptr, E_DIM, 3 * E_DIM, 3 * E_DIM, SEQ, scale,
        (long)SEQ * 3 * E_DIM, (long)SEQ * 3 * E_DIM, (long)SEQ * SEQ);

    // 3) row softmax (8192 rows of 2048)
    softmax_rows_2048<<<BATCH * SEQ, 256>>>(sc);

    // 4) attn_out = attn @ v, batched over B  (NN)
    mm_tf32<0, 0><<<dim3(8, 16, BATCH), 256, SMEM_BYTES>>>(
        sc, qkv + 2 * E_DIM, ao, nullptr, SEQ, SEQ, 3 * E_DIM, E_DIM, 1.0f,
        (long)SEQ * SEQ, (long)SEQ * 3 * E_DIM, (long)SEQ * E_DIM);

    // 5) out = attn_out @ w_out^T
    mm_tf32<1, 0><<<dim3(8, 64, 1), 256, SMEM_BYTES>>>(
        ao, w_out, oo, nullptr, E_DIM, E_DIM, E_DIM, E_DIM, 1.0f, 0, 0, 0);

    // 6) final = out * sigmoid(out @ gate_w^T)   (gated epilogue)
    mm_tf32<1, 1><<<dim3(8, 64, 1), 256, SMEM_BYTES>>>(
        oo, g_w, out, oo, E_DIM, E_DIM, E_DIM, E_DIM, 1.0f, 0, 0, 0);
}